// round 4
// baseline (speedup 1.0000x reference)
#include <cuda_runtime.h>
#include <cuda_bf16.h>
#include <math.h>

// Problem constants
#define BB 2
#define NN 8192
#define II 32
#define EE 128
#define HH 64
#define RR 4

// Scratch (device globals; no allocation allowed)
__device__ float    g_u[BB * NN * HH];       // u[b,n,k] = pf @ Wd1^T   (4 MB)
__device__ float    g_pe[BB * II * EE];      // pos_embed
__device__ float    g_v1[BB * II * HH];      // pe @ Wd1^T + bd1
__device__ float    g_v2[BB * II * HH];      // (pe-ne) @ Wd1^T + bd1
__device__ float    g_M[HH * HH];            // M[k][c] = sum_e Wd1[k][e]*W2[e][c]
__device__ float    g_MB2[RR * HH];          // MB2t[r][k] = sum_e Wd1[k][e]*B2[e][r]
__device__ int      g_inter[BB * II * II];   // pairwise mask intersections
__device__ float    g_pf_fallback[BB * NN * EE]; // used only if out_size too small

// ---------------------------------------------------------------------------
// threefry2x32 with key = jax.random.key(42) -> (0, 42), 20 rounds
// ---------------------------------------------------------------------------
__device__ __forceinline__ void threefry2x32_42(unsigned c0, unsigned c1,
                                                unsigned& y0, unsigned& y1) {
    const unsigned ks0 = 0u, ks1 = 42u;
    const unsigned ks2 = 0x1BD11BDAu ^ ks0 ^ ks1;
    unsigned x0 = c0 + ks0;
    unsigned x1 = c1 + ks1;
#define TF_R(r) { x0 += x1; x1 = (x1 << (r)) | (x1 >> (32 - (r))); x1 ^= x0; }
    TF_R(13) TF_R(15) TF_R(26) TF_R(6)
    x0 += ks1; x1 += ks2 + 1u;
    TF_R(17) TF_R(29) TF_R(16) TF_R(24)
    x0 += ks2; x1 += ks0 + 2u;
    TF_R(13) TF_R(15) TF_R(26) TF_R(6)
    x0 += ks0; x1 += ks1 + 3u;
    TF_R(17) TF_R(29) TF_R(16) TF_R(24)
    x0 += ks1; x1 += ks2 + 4u;
    TF_R(13) TF_R(15) TF_R(26) TF_R(6)
    x0 += ks2; x1 += ks0 + 5u;
#undef TF_R
    y0 = x0; y1 = x1;
}

// ---------------------------------------------------------------------------
// K0a: precompute M = Wd1@W2, MB2t = (Wd1@B2)^T, zero g_inter
// ---------------------------------------------------------------------------
__global__ void k_prep(const float* __restrict__ Wd1,
                       const float* __restrict__ W2,
                       const float* __restrict__ B2) {
    int t = threadIdx.x;
    if (blockIdx.x == 0) {
        for (int idx = t; idx < BB * II * II; idx += 256) g_inter[idx] = 0;
        {
            int r = t >> 6, k = t & 63;
            float a0 = 0.f, a1 = 0.f;
            for (int e = 0; e < EE; e += 2) {
                a0 = fmaf(Wd1[k * EE + e],     B2[e * RR + r],       a0);
                a1 = fmaf(Wd1[k * EE + e + 1], B2[(e + 1) * RR + r], a1);
            }
            g_MB2[t] = a0 + a1;
        }
    } else {
        int base = (blockIdx.x - 1) * 2048;
        for (int q = 0; q < 8; q++) {
            int idx = base + t * 8 + q;
            int k = idx >> 6, c = idx & 63;
            float a0 = 0.f, a1 = 0.f, a2 = 0.f, a3 = 0.f;
            for (int e = 0; e < EE; e += 4) {
                a0 = fmaf(Wd1[k * EE + e],     W2[e * HH + c],       a0);
                a1 = fmaf(Wd1[k * EE + e + 1], W2[(e + 1) * HH + c], a1);
                a2 = fmaf(Wd1[k * EE + e + 2], W2[(e + 2) * HH + c], a2);
                a3 = fmaf(Wd1[k * EE + e + 3], W2[(e + 3) * HH + c], a3);
            }
            g_M[idx] = (a0 + a1) + (a2 + a3);
        }
    }
}

// ---------------------------------------------------------------------------
// K0b: pos_embed and v1 = pe@Wd1^T + bd1.  grid 64 x 128 (block = (b,i))
// ---------------------------------------------------------------------------
__global__ void k_posemb(const float* __restrict__ pos_coords,
                         const float* __restrict__ Wp,
                         const float* __restrict__ bp,
                         const float* __restrict__ Wd1,
                         const float* __restrict__ bd1) {
    int bi = blockIdx.x;
    int t  = threadIdx.x;
    __shared__ float s_pe[EE];
    float c0 = pos_coords[bi * 3 + 0];
    float c1 = pos_coords[bi * 3 + 1];
    float c2 = pos_coords[bi * 3 + 2];
    if (t < EE) {
        float pe = fmaf(c2, Wp[t * 3 + 2], fmaf(c1, Wp[t * 3 + 1], fmaf(c0, Wp[t * 3 + 0], bp[t])));
        s_pe[t] = pe;
        g_pe[bi * EE + t] = pe;
    }
    __syncthreads();
    if (t < HH) {
        float a0 = 0.f, a1 = 0.f, a2 = 0.f, a3 = 0.f;
        const float* w = Wd1 + t * EE;
        for (int e = 0; e < EE; e += 4) {
            a0 = fmaf(s_pe[e],     w[e],     a0);
            a1 = fmaf(s_pe[e + 1], w[e + 1], a1);
            a2 = fmaf(s_pe[e + 2], w[e + 2], a2);
            a3 = fmaf(s_pe[e + 3], w[e + 3], a3);
        }
        g_v1[bi * HH + t] = ((a0 + a1) + (a2 + a3)) + bd1[t];
    }
}

// ---------------------------------------------------------------------------
// K1: encoder — point_feats (output) + u = pf@Wd1^T (via folded M).
// grid 128 x 128, thread = one point.
// ---------------------------------------------------------------------------
__global__ __launch_bounds__(128) void k_encoder(
    const float* __restrict__ points,
    const float* __restrict__ W1, const float* __restrict__ A1,
    const float* __restrict__ B1, const float* __restrict__ W2,
    const float* __restrict__ A2, const float* __restrict__ B2,
    float* __restrict__ out_pf) {
    extern __shared__ float sm[];
    float* sW2t  = sm;             // [c][e] 64*128
    float* sMt   = sm + 8192;      // [c][k] 64*64
    float* sB2t  = sm + 12288;     // [r][e] 4*128
    float* sMB2t = sm + 12800;     // [r][k] 4*64
    float* sW1   = sm + 13056;     // 64*3
    float* sB1   = sm + 13248;     // 64*4
    float* sA2   = sm + 13504;     // 4*64
    float* sA1   = sm + 13760;     // 12

    int t = threadIdx.x;
    for (int idx = t; idx < 8192; idx += 128) {
        int c = idx >> 7, e = idx & 127;
        sW2t[idx] = W2[e * HH + c];
    }
    for (int idx = t; idx < 4096; idx += 128) {
        int c = idx >> 6, k = idx & 63;
        sMt[idx] = g_M[k * HH + c];
    }
    for (int idx = t; idx < 512; idx += 128) {
        int r = idx >> 7, e = idx & 127;
        sB2t[idx] = B2[e * RR + r];
    }
    for (int idx = t; idx < 256; idx += 128) sMB2t[idx] = g_MB2[idx];
    for (int idx = t; idx < 192; idx += 128) sW1[idx] = W1[idx];
    for (int idx = t; idx < 256; idx += 128) sB1[idx] = B1[idx];
    for (int idx = t; idx < 256; idx += 128) sA2[idx] = A2[idx];
    if (t < 12) sA1[t] = A1[t];
    __syncthreads();

    int n = blockIdx.x * 128 + t;   // 0..16383
    float p0 = points[n * 3 + 0];
    float p1 = points[n * 3 + 1];
    float p2 = points[n * 3 + 2];

    float t1[RR];
#pragma unroll
    for (int r = 0; r < RR; r++)
        t1[r] = fmaf(p2, sA1[r * 3 + 2], fmaf(p1, sA1[r * 3 + 1], p0 * sA1[r * 3 + 0]));

    float pf[EE];
    float u[HH];
    float t2[RR];
#pragma unroll
    for (int e = 0; e < EE; e++) pf[e] = 0.f;
#pragma unroll
    for (int k = 0; k < HH; k++) u[k] = 0.f;
#pragma unroll
    for (int r = 0; r < RR; r++) t2[r] = 0.f;

#pragma unroll 1
    for (int c = 0; c < 64; c++) {
        float hc = fmaf(p2, sW1[c * 3 + 2], fmaf(p1, sW1[c * 3 + 1], p0 * sW1[c * 3 + 0]));
        float lb = fmaf(t1[3], sB1[c * 4 + 3],
                   fmaf(t1[2], sB1[c * 4 + 2],
                   fmaf(t1[1], sB1[c * 4 + 1], t1[0] * sB1[c * 4 + 0])));
        hc = fmaf(0.25f, lb, hc);
        hc = fmaxf(hc, 0.0f);
        t2[0] = fmaf(hc, sA2[c],       t2[0]);
        t2[1] = fmaf(hc, sA2[64 + c],  t2[1]);
        t2[2] = fmaf(hc, sA2[128 + c], t2[2]);
        t2[3] = fmaf(hc, sA2[192 + c], t2[3]);
        const float* w2r = sW2t + (c << 7);
#pragma unroll
        for (int e = 0; e < EE; e++) pf[e] = fmaf(hc, w2r[e], pf[e]);
        const float* mr = sMt + (c << 6);
#pragma unroll
        for (int k = 0; k < HH; k++) u[k] = fmaf(hc, mr[k], u[k]);
    }

#pragma unroll
    for (int r = 0; r < RR; r++) {
        float s = 0.25f * t2[r];
        const float* b2r = sB2t + r * EE;
#pragma unroll
        for (int e = 0; e < EE; e++) pf[e] = fmaf(s, b2r[e], pf[e]);
        const float* mb = sMB2t + r * HH;
#pragma unroll
        for (int k = 0; k < HH; k++) u[k] = fmaf(s, mb[k], u[k]);
    }

    float* op = out_pf + (size_t)n * EE;
#pragma unroll
    for (int e = 0; e < EE; e += 4)
        *(float4*)(op + e) = make_float4(pf[e], pf[e + 1], pf[e + 2], pf[e + 3]);
    float* up = g_u + (size_t)n * HH;
#pragma unroll
    for (int k = 0; k < HH; k += 4)
        *(float4*)(up + k) = make_float4(u[k], u[k + 1], u[k + 2], u[k + 3]);
}

// ---------------------------------------------------------------------------
// K2: initial masks + intersection counts.  grid 64 x 256 (block = (b, n-chunk))
// ---------------------------------------------------------------------------
__global__ __launch_bounds__(256) void k_mask(const float* __restrict__ Wd2,
                                              const float* __restrict__ bd2) {
    __shared__ float sv[II * HH];
    __shared__ float sw[HH];
    __shared__ float sb;
    int t = threadIdx.x;
    int b = blockIdx.x >> 5;
    int chunk = blockIdx.x & 31;
    for (int idx = t; idx < II * HH; idx += 256) sv[idx] = g_v1[b * II * HH + idx];
    if (t < HH) sw[t] = Wd2[t];
    if (t == 0) sb = bd2[0];
    __syncthreads();

    int n = (chunk << 8) + t;
    const float* up = g_u + ((size_t)(b * NN + n)) * HH;
    float uu[HH];
#pragma unroll
    for (int k = 0; k < HH; k += 4) {
        float4 v = *(const float4*)(up + k);
        uu[k] = v.x; uu[k + 1] = v.y; uu[k + 2] = v.z; uu[k + 3] = v.w;
    }
    int lane = t & 31;
    unsigned myword = 0;
#pragma unroll 1
    for (int i = 0; i < II; i++) {
        const float* vv = sv + (i << 6);
        float a0 = 0.f, a1 = 0.f;
#pragma unroll
        for (int k = 0; k < HH; k += 2) {
            a0 = fmaf(fmaxf(uu[k] + vv[k], 0.f),         sw[k],     a0);
            a1 = fmaf(fmaxf(uu[k + 1] + vv[k + 1], 0.f), sw[k + 1], a1);
        }
        float logit = a0 + a1 + sb;
        unsigned bal = __ballot_sync(0xffffffffu, logit > 0.0f);
        if (lane == i) myword = bal;
    }
#pragma unroll 1
    for (int j = 0; j < II; j++) {
        unsigned wj = __shfl_sync(0xffffffffu, myword, j);
        int cnt = __popc(myword & wj);
        atomicAdd(&g_inter[(b * II + lane) * II + j], cnt);
    }
}

// ---------------------------------------------------------------------------
// K3: IoU + Gumbel-max selection (JAX partitionable threefry) + v2. grid 64x128
// ---------------------------------------------------------------------------
__global__ void k_select(const float* __restrict__ pos_coords,
                         const float* __restrict__ Wp,
                         const float* __restrict__ bp,
                         const float* __restrict__ Wd1,
                         const float* __restrict__ bd1) {
    int bi = blockIdx.x;
    int b = bi >> 5, i = bi & 31;
    int t = threadIdx.x;
    __shared__ float s_nc[3];
    __shared__ float s_diff[EE];

    if (t < 32) {
        int j = t;
        float inter_ij = (float)g_inter[(b * II + i) * II + j];
        float mi = (float)g_inter[(b * II + i) * II + i];
        float mj = (float)g_inter[(b * II + j) * II + j];
        float uni = mi + mj - inter_ij;
        float iou = inter_ij / (uni + 1e-6f);
        bool cand = (j != i) && (iou >= 0.1f);
        // JAX partitionable threefry (default since 0.4.36):
        //   bits[l] = y0 ^ y1 of threefry2x32(key, (l >> 32, l & 0xffffffff))
        unsigned l = (unsigned)((b * II + i) * II + j);
        unsigned o0, o1;
        threefry2x32_42(0u, l, o0, o1);
        unsigned bits = o0 ^ o1;
        unsigned score = bits >> 9;                       // monotone in uniform/gumbel
        unsigned key = cand ? ((score << 6) | (unsigned)(31 - j)) : 0u;
        unsigned candmask = __ballot_sync(0xffffffffu, cand);
#pragma unroll
        for (int off = 16; off > 0; off >>= 1) {
            unsigned k2 = __shfl_xor_sync(0xffffffffu, key, off);
            key = (k2 > key) ? k2 : key;
        }
        if (t == 0) {
            if (candmask) {
                int idx = 31 - (int)(key & 63u);
                s_nc[0] = pos_coords[(b * II + idx) * 3 + 0];
                s_nc[1] = pos_coords[(b * II + idx) * 3 + 1];
                s_nc[2] = pos_coords[(b * II + idx) * 3 + 2];
            } else {
                s_nc[0] = 0.f; s_nc[1] = 0.f; s_nc[2] = 0.f;
            }
        }
    }
    __syncthreads();
    if (t < EE) {
        float ne = fmaf(s_nc[2], Wp[t * 3 + 2],
                   fmaf(s_nc[1], Wp[t * 3 + 1],
                   fmaf(s_nc[0], Wp[t * 3 + 0], bp[t])));
        s_diff[t] = g_pe[bi * EE + t] - ne;
    }
    __syncthreads();
    if (t < HH) {
        float a0 = 0.f, a1 = 0.f, a2 = 0.f, a3 = 0.f;
        const float* w = Wd1 + t * EE;
        for (int e = 0; e < EE; e += 4) {
            a0 = fmaf(s_diff[e],     w[e],     a0);
            a1 = fmaf(s_diff[e + 1], w[e + 1], a1);
            a2 = fmaf(s_diff[e + 2], w[e + 2], a2);
            a3 = fmaf(s_diff[e + 3], w[e + 3], a3);
        }
        g_v2[bi * HH + t] = ((a0 + a1) + (a2 + a3)) + bd1[t];
    }
}

// ---------------------------------------------------------------------------
// K4: refined logits.  grid 64 x 256 (block = (b, n-chunk))
// ---------------------------------------------------------------------------
__global__ __launch_bounds__(256) void k_refine(const float* __restrict__ Wd2,
                                                const float* __restrict__ bd2,
                                                float* __restrict__ out) {
    __shared__ float sv[II * HH];
    __shared__ float sw[HH];
    __shared__ float sb;
    int t = threadIdx.x;
    int b = blockIdx.x >> 5;
    int chunk = blockIdx.x & 31;
    for (int idx = t; idx < II * HH; idx += 256) sv[idx] = g_v2[b * II * HH + idx];
    if (t < HH) sw[t] = Wd2[t];
    if (t == 0) sb = bd2[0];
    __syncthreads();

    int n = (chunk << 8) + t;
    const float* up = g_u + ((size_t)(b * NN + n)) * HH;
    float uu[HH];
#pragma unroll
    for (int k = 0; k < HH; k += 4) {
        float4 v = *(const float4*)(up + k);
        uu[k] = v.x; uu[k + 1] = v.y; uu[k + 2] = v.z; uu[k + 3] = v.w;
    }
#pragma unroll 1
    for (int i = 0; i < II; i++) {
        const float* vv = sv + (i << 6);
        float a0 = 0.f, a1 = 0.f;
#pragma unroll
        for (int k = 0; k < HH; k += 2) {
            a0 = fmaf(fmaxf(uu[k] + vv[k], 0.f),         sw[k],     a0);
            a1 = fmaf(fmaxf(uu[k + 1] + vv[k + 1], 0.f), sw[k + 1], a1);
        }
        out[((size_t)(b * II + i) << 13) + n] = a0 + a1 + sb;
    }
}

// ---------------------------------------------------------------------------
extern "C" void kernel_launch(void* const* d_in, const int* in_sizes, int n_in,
                              void* d_out, int out_size) {
    const float* points     = (const float*)d_in[0];
    const float* pos_coords = (const float*)d_in[1];
    const float* W1  = (const float*)d_in[2];
    const float* A1  = (const float*)d_in[3];
    const float* B1  = (const float*)d_in[4];
    const float* W2  = (const float*)d_in[5];
    const float* A2  = (const float*)d_in[6];
    const float* B2  = (const float*)d_in[7];
    const float* Wp  = (const float*)d_in[8];
    const float* bp  = (const float*)d_in[9];
    const float* Wd1 = (const float*)d_in[10];
    const float* bd1 = (const float*)d_in[11];
    const float* Wd2 = (const float*)d_in[12];
    const float* bd2 = (const float*)d_in[13];

    float* out_refined = (float*)d_out;                        // [2,32,8192]
    float* out_pf;                                             // [2,8192,128]
    const int need = BB * II * NN + BB * NN * EE;
    if (out_size >= need) {
        out_pf = (float*)d_out + (size_t)BB * II * NN;
    } else {
        // defensive: don't overrun the harness buffer
        cudaGetSymbolAddress((void**)&out_pf, g_pf_fallback);
    }

    (void)in_sizes; (void)n_in;

    static const int enc_smem = 13776 * 4;
    cudaFuncSetAttribute(k_encoder, cudaFuncAttributeMaxDynamicSharedMemorySize, enc_smem);

    k_prep<<<3, 256>>>(Wd1, W2, B2);
    k_posemb<<<64, 128>>>(pos_coords, Wp, bp, Wd1, bd1);
    k_encoder<<<128, 128, enc_smem>>>(points, W1, A1, B1, W2, A2, B2, out_pf);
    k_mask<<<64, 256>>>(Wd2, bd2);
    k_select<<<64, 128>>>(pos_coords, Wp, bp, Wd1, bd1);
    k_refine<<<64, 256>>>(Wd2, bd2, out_refined);
}

// round 5
// speedup vs baseline: 1.3005x; 1.3005x over previous
#include <cuda_runtime.h>
#include <cuda_bf16.h>
#include <math.h>

#define BB 2
#define NN 8192
#define II 32
#define EE 128
#define HH 64
#define RR 4

// Scratch (device globals)
__device__ float    g_u[BB * NN * HH];        // u[b,n,k] = pf @ Wd1^T (4 MB)
__device__ float    g_pe[BB * II * EE];
__device__ float    g_v1[BB * II * HH];
__device__ float    g_v2[BB * II * HH];
__device__ float    g_M[HH * HH];             // M[k][c] = sum_e Wd1[k][e]*W2[e][c]
__device__ float    g_MB2[RR * HH];
__device__ int      g_inter[BB * II * II];
__device__ unsigned g_maskbits[BB * II * (NN / 32)];   // packed masks
__device__ float    g_pf_fallback[BB * NN * EE];

// ---------------------------------------------------------------------------
// threefry2x32, key = jax.random.key(42) -> (0, 42)
// ---------------------------------------------------------------------------
__device__ __forceinline__ void threefry2x32_42(unsigned c0, unsigned c1,
                                                unsigned& y0, unsigned& y1) {
    const unsigned ks0 = 0u, ks1 = 42u;
    const unsigned ks2 = 0x1BD11BDAu ^ ks0 ^ ks1;
    unsigned x0 = c0 + ks0;
    unsigned x1 = c1 + ks1;
#define TF_R(r) { x0 += x1; x1 = (x1 << (r)) | (x1 >> (32 - (r))); x1 ^= x0; }
    TF_R(13) TF_R(15) TF_R(26) TF_R(6)
    x0 += ks1; x1 += ks2 + 1u;
    TF_R(17) TF_R(29) TF_R(16) TF_R(24)
    x0 += ks2; x1 += ks0 + 2u;
    TF_R(13) TF_R(15) TF_R(26) TF_R(6)
    x0 += ks0; x1 += ks1 + 3u;
    TF_R(17) TF_R(29) TF_R(16) TF_R(24)
    x0 += ks1; x1 += ks2 + 4u;
    TF_R(13) TF_R(15) TF_R(26) TF_R(6)
    x0 += ks2; x1 += ks0 + 5u;
#undef TF_R
    y0 = x0; y1 = x1;
}

// ---------------------------------------------------------------------------
// K0a: M = Wd1@W2, MB2t = (Wd1@B2)^T, zero g_inter
// ---------------------------------------------------------------------------
__global__ void k_prep(const float* __restrict__ Wd1,
                       const float* __restrict__ W2,
                       const float* __restrict__ B2) {
    int t = threadIdx.x;
    if (blockIdx.x == 0) {
        for (int idx = t; idx < BB * II * II; idx += 256) g_inter[idx] = 0;
        {
            int r = t >> 6, k = t & 63;
            float a0 = 0.f, a1 = 0.f;
            for (int e = 0; e < EE; e += 2) {
                a0 = fmaf(Wd1[k * EE + e],     B2[e * RR + r],       a0);
                a1 = fmaf(Wd1[k * EE + e + 1], B2[(e + 1) * RR + r], a1);
            }
            g_MB2[t] = a0 + a1;
        }
    } else {
        int base = (blockIdx.x - 1) * 2048;
        for (int q = 0; q < 8; q++) {
            int idx = base + t * 8 + q;
            int k = idx >> 6, c = idx & 63;
            float a0 = 0.f, a1 = 0.f, a2 = 0.f, a3 = 0.f;
            for (int e = 0; e < EE; e += 4) {
                a0 = fmaf(Wd1[k * EE + e],     W2[e * HH + c],       a0);
                a1 = fmaf(Wd1[k * EE + e + 1], W2[(e + 1) * HH + c], a1);
                a2 = fmaf(Wd1[k * EE + e + 2], W2[(e + 2) * HH + c], a2);
                a3 = fmaf(Wd1[k * EE + e + 3], W2[(e + 3) * HH + c], a3);
            }
            g_M[idx] = (a0 + a1) + (a2 + a3);
        }
    }
}

// ---------------------------------------------------------------------------
// K0b: pos_embed + v1 = pe@Wd1^T + bd1.  grid 64 x 128
// ---------------------------------------------------------------------------
__global__ void k_posemb(const float* __restrict__ pos_coords,
                         const float* __restrict__ Wp,
                         const float* __restrict__ bp,
                         const float* __restrict__ Wd1,
                         const float* __restrict__ bd1) {
    int bi = blockIdx.x;
    int t  = threadIdx.x;
    __shared__ float s_pe[EE];
    float c0 = pos_coords[bi * 3 + 0];
    float c1 = pos_coords[bi * 3 + 1];
    float c2 = pos_coords[bi * 3 + 2];
    if (t < EE) {
        float pe = fmaf(c2, Wp[t * 3 + 2], fmaf(c1, Wp[t * 3 + 1], fmaf(c0, Wp[t * 3 + 0], bp[t])));
        s_pe[t] = pe;
        g_pe[bi * EE + t] = pe;
    }
    __syncthreads();
    if (t < HH) {
        float a0 = 0.f, a1 = 0.f, a2 = 0.f, a3 = 0.f;
        const float* w = Wd1 + t * EE;
        for (int e = 0; e < EE; e += 4) {
            a0 = fmaf(s_pe[e],     w[e],     a0);
            a1 = fmaf(s_pe[e + 1], w[e + 1], a1);
            a2 = fmaf(s_pe[e + 2], w[e + 2], a2);
            a3 = fmaf(s_pe[e + 3], w[e + 3], a3);
        }
        g_v1[bi * HH + t] = ((a0 + a1) + (a2 + a3)) + bd1[t];
    }
}

// ---------------------------------------------------------------------------
// K1: encoder, 2 threads per point (half-split over output dims).
// grid 256 x 128: blockIdx>>7 = half, blockIdx&127 = 128-point tile.
// ---------------------------------------------------------------------------
__global__ __launch_bounds__(128) void k_encoder(
    const float* __restrict__ points,
    const float* __restrict__ W1, const float* __restrict__ A1,
    const float* __restrict__ B1, const float* __restrict__ W2,
    const float* __restrict__ A2, const float* __restrict__ B2,
    float* __restrict__ out_pf) {
    __shared__ float sW2h[64 * 64];    // [c][e'] this half's W2^T
    __shared__ float sMh[64 * 32];     // [c][k'] this half's M^T
    __shared__ float sB2h[RR * 64];    // [r][e']
    __shared__ float sMB2h[RR * 32];   // [r][k']
    __shared__ float sW1[64 * 3];
    __shared__ float sB1[64 * 4];
    __shared__ float sA2[4 * 64];
    __shared__ float sA1[12];

    int t    = threadIdx.x;
    int half = blockIdx.x >> 7;
    int blk  = blockIdx.x & 127;
    int eoff = half << 6;     // 0 or 64
    int koff = half << 5;     // 0 or 32

    for (int idx = t; idx < 4096; idx += 128) {
        int c = idx >> 6, e = idx & 63;
        sW2h[idx] = W2[(eoff + e) * HH + c];
    }
    for (int idx = t; idx < 2048; idx += 128) {
        int c = idx >> 5, k = idx & 31;
        sMh[idx] = g_M[(koff + k) * HH + c];
    }
    for (int idx = t; idx < 256; idx += 128) {
        int r = idx >> 6, e = idx & 63;
        sB2h[idx] = B2[(eoff + e) * RR + r];
    }
    if (t < 128) {
        int r = t >> 5, k = t & 31;
        sMB2h[t] = g_MB2[r * HH + koff + k];
    }
    for (int idx = t; idx < 192; idx += 128) sW1[idx] = W1[idx];
    for (int idx = t; idx < 256; idx += 128) sB1[idx] = B1[idx];
    for (int idx = t; idx < 256; idx += 128) sA2[idx] = A2[idx];
    if (t < 12) sA1[t] = A1[t];
    __syncthreads();

    int n = (blk << 7) + t;   // 0..16383
    float p0 = points[n * 3 + 0];
    float p1 = points[n * 3 + 1];
    float p2 = points[n * 3 + 2];

    float t1[RR];
#pragma unroll
    for (int r = 0; r < RR; r++)
        t1[r] = fmaf(p2, sA1[r * 3 + 2], fmaf(p1, sA1[r * 3 + 1], p0 * sA1[r * 3 + 0]));

    float pf[64];
    float u[32];
    float t2[RR];
#pragma unroll
    for (int e = 0; e < 64; e++) pf[e] = 0.f;
#pragma unroll
    for (int k = 0; k < 32; k++) u[k] = 0.f;
#pragma unroll
    for (int r = 0; r < RR; r++) t2[r] = 0.f;

#pragma unroll 1
    for (int c = 0; c < 64; c++) {
        float hc = fmaf(p2, sW1[c * 3 + 2], fmaf(p1, sW1[c * 3 + 1], p0 * sW1[c * 3 + 0]));
        float lb = fmaf(t1[3], sB1[c * 4 + 3],
                   fmaf(t1[2], sB1[c * 4 + 2],
                   fmaf(t1[1], sB1[c * 4 + 1], t1[0] * sB1[c * 4 + 0])));
        hc = fmaf(0.25f, lb, hc);
        hc = fmaxf(hc, 0.0f);
        t2[0] = fmaf(hc, sA2[c],       t2[0]);
        t2[1] = fmaf(hc, sA2[64 + c],  t2[1]);
        t2[2] = fmaf(hc, sA2[128 + c], t2[2]);
        t2[3] = fmaf(hc, sA2[192 + c], t2[3]);
        const float* w2r = sW2h + (c << 6);
#pragma unroll
        for (int e = 0; e < 64; e++) pf[e] = fmaf(hc, w2r[e], pf[e]);
        const float* mr = sMh + (c << 5);
#pragma unroll
        for (int k = 0; k < 32; k++) u[k] = fmaf(hc, mr[k], u[k]);
    }

#pragma unroll
    for (int r = 0; r < RR; r++) {
        float s = 0.25f * t2[r];
        const float* b2r = sB2h + (r << 6);
#pragma unroll
        for (int e = 0; e < 64; e++) pf[e] = fmaf(s, b2r[e], pf[e]);
        const float* mb = sMB2h + (r << 5);
#pragma unroll
        for (int k = 0; k < 32; k++) u[k] = fmaf(s, mb[k], u[k]);
    }

    float* op = out_pf + (size_t)n * EE + eoff;
#pragma unroll
    for (int e = 0; e < 64; e += 4)
        *(float4*)(op + e) = make_float4(pf[e], pf[e + 1], pf[e + 2], pf[e + 3]);
    float* up = g_u + (size_t)n * HH + koff;
#pragma unroll
    for (int k = 0; k < 32; k += 4)
        *(float4*)(up + k) = make_float4(u[k], u[k + 1], u[k + 2], u[k + 3]);
}

// ---------------------------------------------------------------------------
// K2: mask bits.  grid 256 (b x igroup(2) x 64 chunks) x 128 threads
// ---------------------------------------------------------------------------
__global__ __launch_bounds__(128) void k_maskbits(const float* __restrict__ Wd2,
                                                  const float* __restrict__ bd2) {
    __shared__ float sv[16 * HH];
    __shared__ float sw[HH];
    __shared__ float sb;
    int t = threadIdx.x;
    int b = blockIdx.x >> 7;
    int ig = (blockIdx.x >> 6) & 1;
    int chunk = blockIdx.x & 63;
    for (int idx = t; idx < 16 * HH; idx += 128)
        sv[idx] = g_v1[b * II * HH + ig * 16 * HH + idx];
    if (t < HH) sw[t] = Wd2[t];
    if (t == 0) sb = bd2[0];
    __syncthreads();

    int n = (chunk << 7) + t;
    const float* up = g_u + ((size_t)(b * NN + n)) * HH;
    float uu[HH];
#pragma unroll
    for (int k = 0; k < HH; k += 4) {
        float4 v = *(const float4*)(up + k);
        uu[k] = v.x; uu[k + 1] = v.y; uu[k + 2] = v.z; uu[k + 3] = v.w;
    }
    int w = t >> 5, lane = t & 31;
#pragma unroll 1
    for (int ii = 0; ii < 16; ii++) {
        const float* vv = sv + (ii << 6);
        float a0 = 0.f, a1 = 0.f, a2 = 0.f, a3 = 0.f;
#pragma unroll
        for (int k = 0; k < HH; k += 4) {
            a0 = fmaf(fmaxf(uu[k]     + vv[k],     0.f), sw[k],     a0);
            a1 = fmaf(fmaxf(uu[k + 1] + vv[k + 1], 0.f), sw[k + 1], a1);
            a2 = fmaf(fmaxf(uu[k + 2] + vv[k + 2], 0.f), sw[k + 2], a2);
            a3 = fmaf(fmaxf(uu[k + 3] + vv[k + 3], 0.f), sw[k + 3], a3);
        }
        float logit = ((a0 + a1) + (a2 + a3)) + sb;
        unsigned bal = __ballot_sync(0xffffffffu, logit > 0.0f);
        if (lane == 0)
            g_maskbits[(b * II + ig * 16 + ii) * (NN / 32) + (chunk << 2) + w] = bal;
    }
}

// ---------------------------------------------------------------------------
// K2b: pairwise intersections from bitmap.  grid 16 (b x 8 wchunks) x 1024
// ---------------------------------------------------------------------------
__global__ __launch_bounds__(1024) void k_inter() {
    __shared__ unsigned s_w[II * 33];
    int b = blockIdx.x >> 3;
    int wc = blockIdx.x & 7;
    int t = threadIdx.x;
    {
        int i = t >> 5, w = t & 31;
        s_w[i * 33 + w] = g_maskbits[(b * II + i) * (NN / 32) + (wc << 5) + w];
    }
    __syncthreads();
    int i = t >> 5, j = t & 31;
    int sum = 0;
#pragma unroll
    for (int w = 0; w < 32; w++)
        sum += __popc(s_w[i * 33 + w] & s_w[j * 33 + w]);
    atomicAdd(&g_inter[(b * II + i) * II + j], sum);
}

// ---------------------------------------------------------------------------
// K3: IoU + Gumbel-max (JAX partitionable threefry) + v2.  grid 64 x 128
// ---------------------------------------------------------------------------
__global__ void k_select(const float* __restrict__ pos_coords,
                         const float* __restrict__ Wp,
                         const float* __restrict__ bp,
                         const float* __restrict__ Wd1,
                         const float* __restrict__ bd1) {
    int bi = blockIdx.x;
    int b = bi >> 5, i = bi & 31;
    int t = threadIdx.x;
    __shared__ float s_nc[3];
    __shared__ float s_diff[EE];

    if (t < 32) {
        int j = t;
        float inter_ij = (float)g_inter[(b * II + i) * II + j];
        float mi = (float)g_inter[(b * II + i) * II + i];
        float mj = (float)g_inter[(b * II + j) * II + j];
        float uni = mi + mj - inter_ij;
        float iou = inter_ij / (uni + 1e-6f);
        bool cand = (j != i) && (iou >= 0.1f);
        unsigned l = (unsigned)((b * II + i) * II + j);
        unsigned o0, o1;
        threefry2x32_42(0u, l, o0, o1);
        unsigned bits = o0 ^ o1;
        unsigned score = bits >> 9;
        unsigned key = cand ? ((score << 6) | (unsigned)(31 - j)) : 0u;
        unsigned candmask = __ballot_sync(0xffffffffu, cand);
#pragma unroll
        for (int off = 16; off > 0; off >>= 1) {
            unsigned k2 = __shfl_xor_sync(0xffffffffu, key, off);
            key = (k2 > key) ? k2 : key;
        }
        if (t == 0) {
            if (candmask) {
                int idx = 31 - (int)(key & 63u);
                s_nc[0] = pos_coords[(b * II + idx) * 3 + 0];
                s_nc[1] = pos_coords[(b * II + idx) * 3 + 1];
                s_nc[2] = pos_coords[(b * II + idx) * 3 + 2];
            } else {
                s_nc[0] = 0.f; s_nc[1] = 0.f; s_nc[2] = 0.f;
            }
        }
    }
    __syncthreads();
    if (t < EE) {
        float ne = fmaf(s_nc[2], Wp[t * 3 + 2],
                   fmaf(s_nc[1], Wp[t * 3 + 1],
                   fmaf(s_nc[0], Wp[t * 3 + 0], bp[t])));
        s_diff[t] = g_pe[bi * EE + t] - ne;
    }
    __syncthreads();
    if (t < HH) {
        float a0 = 0.f, a1 = 0.f, a2 = 0.f, a3 = 0.f;
        const float* w = Wd1 + t * EE;
        for (int e = 0; e < EE; e += 4) {
            a0 = fmaf(s_diff[e],     w[e],     a0);
            a1 = fmaf(s_diff[e + 1], w[e + 1], a1);
            a2 = fmaf(s_diff[e + 2], w[e + 2], a2);
            a3 = fmaf(s_diff[e + 3], w[e + 3], a3);
        }
        g_v2[bi * HH + t] = ((a0 + a1) + (a2 + a3)) + bd1[t];
    }
}

// ---------------------------------------------------------------------------
// K4: refined logits.  grid 256 (b x ig(2) x 64 chunks) x 128 threads
// ---------------------------------------------------------------------------
__global__ __launch_bounds__(128) void k_refine(const float* __restrict__ Wd2,
                                                const float* __restrict__ bd2,
                                                float* __restrict__ out) {
    __shared__ float sv[16 * HH];
    __shared__ float sw[HH];
    __shared__ float sb;
    int t = threadIdx.x;
    int b = blockIdx.x >> 7;
    int ig = (blockIdx.x >> 6) & 1;
    int chunk = blockIdx.x & 63;
    for (int idx = t; idx < 16 * HH; idx += 128)
        sv[idx] = g_v2[b * II * HH + ig * 16 * HH + idx];
    if (t < HH) sw[t] = Wd2[t];
    if (t == 0) sb = bd2[0];
    __syncthreads();

    int n = (chunk << 7) + t;
    const float* up = g_u + ((size_t)(b * NN + n)) * HH;
    float uu[HH];
#pragma unroll
    for (int k = 0; k < HH; k += 4) {
        float4 v = *(const float4*)(up + k);
        uu[k] = v.x; uu[k + 1] = v.y; uu[k + 2] = v.z; uu[k + 3] = v.w;
    }
#pragma unroll 1
    for (int ii = 0; ii < 16; ii++) {
        const float* vv = sv + (ii << 6);
        float a0 = 0.f, a1 = 0.f, a2 = 0.f, a3 = 0.f;
#pragma unroll
        for (int k = 0; k < HH; k += 4) {
            a0 = fmaf(fmaxf(uu[k]     + vv[k],     0.f), sw[k],     a0);
            a1 = fmaf(fmaxf(uu[k + 1] + vv[k + 1], 0.f), sw[k + 1], a1);
            a2 = fmaf(fmaxf(uu[k + 2] + vv[k + 2], 0.f), sw[k + 2], a2);
            a3 = fmaf(fmaxf(uu[k + 3] + vv[k + 3], 0.f), sw[k + 3], a3);
        }
        out[((size_t)(b * II + ig * 16 + ii) << 13) + n] = ((a0 + a1) + (a2 + a3)) + sb;
    }
}

// ---------------------------------------------------------------------------
extern "C" void kernel_launch(void* const* d_in, const int* in_sizes, int n_in,
                              void* d_out, int out_size) {
    const float* points     = (const float*)d_in[0];
    const float* pos_coords = (const float*)d_in[1];
    const float* W1  = (const float*)d_in[2];
    const float* A1  = (const float*)d_in[3];
    const float* B1  = (const float*)d_in[4];
    const float* W2  = (const float*)d_in[5];
    const float* A2  = (const float*)d_in[6];
    const float* B2  = (const float*)d_in[7];
    const float* Wp  = (const float*)d_in[8];
    const float* bp  = (const float*)d_in[9];
    const float* Wd1 = (const float*)d_in[10];
    const float* bd1 = (const float*)d_in[11];
    const float* Wd2 = (const float*)d_in[12];
    const float* bd2 = (const float*)d_in[13];

    float* out_refined = (float*)d_out;                         // [2,32,8192]
    float* out_pf;                                              // [2,8192,128]
    const int need = BB * II * NN + BB * NN * EE;
    if (out_size >= need) {
        out_pf = (float*)d_out + (size_t)BB * II * NN;
    } else {
        cudaGetSymbolAddress((void**)&out_pf, g_pf_fallback);
    }

    (void)in_sizes; (void)n_in;

    k_prep<<<3, 256>>>(Wd1, W2, B2);
    k_posemb<<<64, 128>>>(pos_coords, Wp, bp, Wd1, bd1);
    k_encoder<<<256, 128>>>(points, W1, A1, B1, W2, A2, B2, out_pf);
    k_maskbits<<<256, 128>>>(Wd2, bd2);
    k_inter<<<16, 1024>>>();
    k_select<<<64, 128>>>(pos_coords, Wp, bp, Wd1, bd1);
    k_refine<<<256, 128>>>(Wd2, bd2, out_refined);
}

// round 6
// speedup vs baseline: 1.3045x; 1.0030x over previous
#include <cuda_runtime.h>
#include <cuda_bf16.h>
#include <math.h>

#define BB 2
#define NN 8192
#define II 32
#define EE 128
#define HH 64
#define RR 4

__device__ float    g_u[BB * NN * HH];        // u[b,n,k] = pf @ Wd1^T (4 MB)
__device__ float    g_pe[BB * II * EE];
__device__ float    g_v1[BB * II * HH];
__device__ float    g_v2[BB * II * HH];
__device__ float    g_M[HH * HH];             // M[k][c] = sum_e Wd1[k][e]*W2[e][c]
__device__ float    g_MB2[RR * HH];
__device__ int      g_inter[BB * II * II];
__device__ unsigned g_maskbits[BB * II * (NN / 32)];
__device__ float    g_pf_fallback[BB * NN * EE];

// ---------------------------------------------------------------------------
// threefry2x32, key = jax.random.key(42) -> (0, 42)
// ---------------------------------------------------------------------------
__device__ __forceinline__ void threefry2x32_42(unsigned c0, unsigned c1,
                                                unsigned& y0, unsigned& y1) {
    const unsigned ks0 = 0u, ks1 = 42u;
    const unsigned ks2 = 0x1BD11BDAu ^ ks0 ^ ks1;
    unsigned x0 = c0 + ks0;
    unsigned x1 = c1 + ks1;
#define TF_R(r) { x0 += x1; x1 = (x1 << (r)) | (x1 >> (32 - (r))); x1 ^= x0; }
    TF_R(13) TF_R(15) TF_R(26) TF_R(6)
    x0 += ks1; x1 += ks2 + 1u;
    TF_R(17) TF_R(29) TF_R(16) TF_R(24)
    x0 += ks2; x1 += ks0 + 2u;
    TF_R(13) TF_R(15) TF_R(26) TF_R(6)
    x0 += ks0; x1 += ks1 + 3u;
    TF_R(17) TF_R(29) TF_R(16) TF_R(24)
    x0 += ks1; x1 += ks2 + 4u;
    TF_R(13) TF_R(15) TF_R(26) TF_R(6)
    x0 += ks2; x1 += ks0 + 5u;
#undef TF_R
    y0 = x0; y1 = x1;
}

// ---------------------------------------------------------------------------
// K0: merged prep (blocks 0-2) + pos_embed/v1 (blocks 3-66).  grid 67 x 256
// ---------------------------------------------------------------------------
__global__ __launch_bounds__(256) void k_prep(const float* __restrict__ Wd1,
                                              const float* __restrict__ W2,
                                              const float* __restrict__ B2,
                                              const float* __restrict__ pos_coords,
                                              const float* __restrict__ Wp,
                                              const float* __restrict__ bp,
                                              const float* __restrict__ bd1) {
    int t = threadIdx.x;
    int bx = blockIdx.x;
    if (bx == 0) {
        for (int idx = t; idx < BB * II * II; idx += 256) g_inter[idx] = 0;
        {
            int r = t >> 6, k = t & 63;
            float a0 = 0.f, a1 = 0.f;
            for (int e = 0; e < EE; e += 2) {
                a0 = fmaf(Wd1[k * EE + e],     B2[e * RR + r],       a0);
                a1 = fmaf(Wd1[k * EE + e + 1], B2[(e + 1) * RR + r], a1);
            }
            g_MB2[t] = a0 + a1;
        }
    } else if (bx <= 2) {
        int base = (bx - 1) * 2048;
        for (int q = 0; q < 8; q++) {
            int idx = base + t * 8 + q;
            int k = idx >> 6, c = idx & 63;
            float a0 = 0.f, a1 = 0.f, a2 = 0.f, a3 = 0.f;
            for (int e = 0; e < EE; e += 4) {
                a0 = fmaf(Wd1[k * EE + e],     W2[e * HH + c],       a0);
                a1 = fmaf(Wd1[k * EE + e + 1], W2[(e + 1) * HH + c], a1);
                a2 = fmaf(Wd1[k * EE + e + 2], W2[(e + 2) * HH + c], a2);
                a3 = fmaf(Wd1[k * EE + e + 3], W2[(e + 3) * HH + c], a3);
            }
            g_M[idx] = (a0 + a1) + (a2 + a3);
        }
    } else {
        int bi = bx - 3;
        __shared__ float s_pe[EE];
        float c0 = pos_coords[bi * 3 + 0];
        float c1 = pos_coords[bi * 3 + 1];
        float c2 = pos_coords[bi * 3 + 2];
        if (t < EE) {
            float pe = fmaf(c2, Wp[t * 3 + 2], fmaf(c1, Wp[t * 3 + 1], fmaf(c0, Wp[t * 3 + 0], bp[t])));
            s_pe[t] = pe;
            g_pe[bi * EE + t] = pe;
        }
        __syncthreads();
        if (t < HH) {
            float a0 = 0.f, a1 = 0.f, a2 = 0.f, a3 = 0.f;
            const float* w = Wd1 + t * EE;
            for (int e = 0; e < EE; e += 4) {
                a0 = fmaf(s_pe[e],     w[e],     a0);
                a1 = fmaf(s_pe[e + 1], w[e + 1], a1);
                a2 = fmaf(s_pe[e + 2], w[e + 2], a2);
                a3 = fmaf(s_pe[e + 3], w[e + 3], a3);
            }
            g_v1[bi * HH + t] = ((a0 + a1) + (a2 + a3)) + bd1[t];
        }
    }
}

// ---------------------------------------------------------------------------
// K1: encoder, 4 threads per point (quarter-split over output dims).
// grid 512 x 128: q = bx>>7 (0..3), blk = bx&127.
// ---------------------------------------------------------------------------
__global__ __launch_bounds__(128) void k_encoder(
    const float* __restrict__ points,
    const float* __restrict__ W1, const float* __restrict__ A1,
    const float* __restrict__ B1, const float* __restrict__ W2,
    const float* __restrict__ A2, const float* __restrict__ B2,
    float* __restrict__ out_pf) {
    __shared__ float sW2q[64 * 32];    // [c][e'] quarter W2^T
    __shared__ float sMq[64 * 16];     // [c][k'] quarter M^T
    __shared__ float sB2q[RR * 32];
    __shared__ float sMB2q[RR * 16];
    __shared__ float sW1[64 * 3];
    __shared__ float sB1[64 * 4];
    __shared__ float sA2[4 * 64];
    __shared__ float sA1[12];

    int t    = threadIdx.x;
    int q    = blockIdx.x >> 7;
    int blk  = blockIdx.x & 127;
    int eoff = q << 5;     // 0,32,64,96
    int koff = q << 4;     // 0,16,32,48

    for (int idx = t; idx < 2048; idx += 128) {
        int c = idx >> 5, e = idx & 31;
        sW2q[idx] = W2[(eoff + e) * HH + c];
    }
    for (int idx = t; idx < 1024; idx += 128) {
        int c = idx >> 4, k = idx & 15;
        sMq[idx] = g_M[(koff + k) * HH + c];
    }
    if (t < 128) {
        int r = t >> 5, e = t & 31;
        sB2q[t] = B2[(eoff + e) * RR + r];
    }
    if (t < 64) {
        int r = t >> 4, k = t & 15;
        sMB2q[t] = g_MB2[r * HH + koff + k];
    }
    for (int idx = t; idx < 192; idx += 128) sW1[idx] = W1[idx];
    for (int idx = t; idx < 256; idx += 128) sB1[idx] = B1[idx];
    for (int idx = t; idx < 256; idx += 128) sA2[idx] = A2[idx];
    if (t < 12) sA1[t] = A1[t];
    __syncthreads();

    int n = (blk << 7) + t;   // 0..16383
    float p0 = points[n * 3 + 0];
    float p1 = points[n * 3 + 1];
    float p2 = points[n * 3 + 2];

    float t1[RR];
#pragma unroll
    for (int r = 0; r < RR; r++)
        t1[r] = fmaf(p2, sA1[r * 3 + 2], fmaf(p1, sA1[r * 3 + 1], p0 * sA1[r * 3 + 0]));

    float pf[32];
    float u[16];
    float t2[RR];
#pragma unroll
    for (int e = 0; e < 32; e++) pf[e] = 0.f;
#pragma unroll
    for (int k = 0; k < 16; k++) u[k] = 0.f;
#pragma unroll
    for (int r = 0; r < RR; r++) t2[r] = 0.f;

#pragma unroll 1
    for (int c = 0; c < 64; c++) {
        float hc = fmaf(p2, sW1[c * 3 + 2], fmaf(p1, sW1[c * 3 + 1], p0 * sW1[c * 3 + 0]));
        float lb = fmaf(t1[3], sB1[c * 4 + 3],
                   fmaf(t1[2], sB1[c * 4 + 2],
                   fmaf(t1[1], sB1[c * 4 + 1], t1[0] * sB1[c * 4 + 0])));
        hc = fmaf(0.25f, lb, hc);
        hc = fmaxf(hc, 0.0f);
        t2[0] = fmaf(hc, sA2[c],       t2[0]);
        t2[1] = fmaf(hc, sA2[64 + c],  t2[1]);
        t2[2] = fmaf(hc, sA2[128 + c], t2[2]);
        t2[3] = fmaf(hc, sA2[192 + c], t2[3]);
        const float* w2r = sW2q + (c << 5);
#pragma unroll
        for (int e = 0; e < 32; e++) pf[e] = fmaf(hc, w2r[e], pf[e]);
        const float* mr = sMq + (c << 4);
#pragma unroll
        for (int k = 0; k < 16; k++) u[k] = fmaf(hc, mr[k], u[k]);
    }

#pragma unroll
    for (int r = 0; r < RR; r++) {
        float s = 0.25f * t2[r];
        const float* b2r = sB2q + (r << 5);
#pragma unroll
        for (int e = 0; e < 32; e++) pf[e] = fmaf(s, b2r[e], pf[e]);
        const float* mb = sMB2q + (r << 4);
#pragma unroll
        for (int k = 0; k < 16; k++) u[k] = fmaf(s, mb[k], u[k]);
    }

    float* op = out_pf + (size_t)n * EE + eoff;
#pragma unroll
    for (int e = 0; e < 32; e += 4)
        *(float4*)(op + e) = make_float4(pf[e], pf[e + 1], pf[e + 2], pf[e + 3]);
    float* up = g_u + (size_t)n * HH + koff;
#pragma unroll
    for (int k = 0; k < 16; k += 4)
        *(float4*)(up + k) = make_float4(u[k], u[k + 1], u[k + 2], u[k + 3]);
}

// ---------------------------------------------------------------------------
// K2: mask bits, k-split across lane halves.
// grid 512 x 128: b = bx>>8, ig = (bx>>7)&1, chunk = bx&127 (64 points each).
// Warp: lane = p(0..15) + 16*h; thread sums its 32-k half, shfl-combines.
// ---------------------------------------------------------------------------
__global__ __launch_bounds__(128) void k_maskbits(const float* __restrict__ Wd2,
                                                  const float* __restrict__ bd2) {
    __shared__ float s_v[16 * 66];          // padded: k + (k>=32)
    __shared__ unsigned s_half[16 * 4];
    __shared__ float sb;
    int t = threadIdx.x;
    int b = blockIdx.x >> 8;
    int ig = (blockIdx.x >> 7) & 1;
    int chunk = blockIdx.x & 127;

    for (int idx = t; idx < 16 * HH; idx += 128) {
        int ii = idx >> 6, k = idx & 63;
        s_v[ii * 66 + k + (k >> 5)] = g_v1[b * II * HH + (ig * 16 + ii) * HH + k];
    }
    if (t == 0) sb = bd2[0];
    __syncthreads();

    int w = t >> 5, lane = t & 31;
    int p = lane & 15, h = lane >> 4;
    int n = (chunk << 6) + (w << 4) + p;
    int koff = h << 5;

    const float* up = g_u + ((size_t)(b * NN + n)) * HH + koff;
    float uu[32], swr[32];
#pragma unroll
    for (int k = 0; k < 32; k += 4) {
        float4 v = *(const float4*)(up + k);
        uu[k] = v.x; uu[k + 1] = v.y; uu[k + 2] = v.z; uu[k + 3] = v.w;
        float4 wv = *(const float4*)(Wd2 + koff + k);
        swr[k] = wv.x; swr[k + 1] = wv.y; swr[k + 2] = wv.z; swr[k + 3] = wv.w;
    }

#pragma unroll 1
    for (int ii = 0; ii < 16; ii++) {
        const float* vv = s_v + ii * 66 + h * 33;
        float a0 = 0.f, a1 = 0.f, a2 = 0.f, a3 = 0.f;
#pragma unroll
        for (int k = 0; k < 32; k += 4) {
            a0 = fmaf(fmaxf(uu[k]     + vv[k],     0.f), swr[k],     a0);
            a1 = fmaf(fmaxf(uu[k + 1] + vv[k + 1], 0.f), swr[k + 1], a1);
            a2 = fmaf(fmaxf(uu[k + 2] + vv[k + 2], 0.f), swr[k + 2], a2);
            a3 = fmaf(fmaxf(uu[k + 3] + vv[k + 3], 0.f), swr[k + 3], a3);
        }
        float tot = (a0 + a1) + (a2 + a3);
        tot += __shfl_xor_sync(0xffffffffu, tot, 16);
        float logit = tot + sb;
        unsigned bal = __ballot_sync(0xffffffffu, logit > 0.0f);
        if (lane == 0) s_half[ii * 4 + w] = bal & 0xFFFFu;
    }
    __syncthreads();
    if (t < 32) {
        int ii = t >> 1, half2 = t & 1;
        unsigned word = s_half[ii * 4 + half2 * 2] | (s_half[ii * 4 + half2 * 2 + 1] << 16);
        g_maskbits[(b * II + ig * 16 + ii) * (NN / 32) + chunk * 2 + half2] = word;
    }
}

// ---------------------------------------------------------------------------
// K2b: pairwise intersections.  grid 16 (b x 8 wchunks) x 1024
// ---------------------------------------------------------------------------
__global__ __launch_bounds__(1024) void k_inter() {
    __shared__ unsigned s_w[II * 33];
    int b = blockIdx.x >> 3;
    int wc = blockIdx.x & 7;
    int t = threadIdx.x;
    {
        int i = t >> 5, w = t & 31;
        s_w[i * 33 + w] = g_maskbits[(b * II + i) * (NN / 32) + (wc << 5) + w];
    }
    __syncthreads();
    int i = t >> 5, j = t & 31;
    int sum = 0;
#pragma unroll
    for (int w = 0; w < 32; w++)
        sum += __popc(s_w[i * 33 + w] & s_w[j * 33 + w]);
    atomicAdd(&g_inter[(b * II + i) * II + j], sum);
}

// ---------------------------------------------------------------------------
// K3: IoU + Gumbel-max (JAX partitionable threefry) + v2.  grid 64 x 128
// ---------------------------------------------------------------------------
__global__ void k_select(const float* __restrict__ pos_coords,
                         const float* __restrict__ Wp,
                         const float* __restrict__ bp,
                         const float* __restrict__ Wd1,
                         const float* __restrict__ bd1) {
    int bi = blockIdx.x;
    int b = bi >> 5, i = bi & 31;
    int t = threadIdx.x;
    __shared__ float s_nc[3];
    __shared__ float s_diff[EE];

    if (t < 32) {
        int j = t;
        float inter_ij = (float)g_inter[(b * II + i) * II + j];
        float mi = (float)g_inter[(b * II + i) * II + i];
        float mj = (float)g_inter[(b * II + j) * II + j];
        float uni = mi + mj - inter_ij;
        float iou = inter_ij / (uni + 1e-6f);
        bool cand = (j != i) && (iou >= 0.1f);
        unsigned l = (unsigned)((b * II + i) * II + j);
        unsigned o0, o1;
        threefry2x32_42(0u, l, o0, o1);
        unsigned bits = o0 ^ o1;
        unsigned score = bits >> 9;
        unsigned key = cand ? ((score << 6) | (unsigned)(31 - j)) : 0u;
        unsigned candmask = __ballot_sync(0xffffffffu, cand);
#pragma unroll
        for (int off = 16; off > 0; off >>= 1) {
            unsigned k2 = __shfl_xor_sync(0xffffffffu, key, off);
            key = (k2 > key) ? k2 : key;
        }
        if (t == 0) {
            if (candmask) {
                int idx = 31 - (int)(key & 63u);
                s_nc[0] = pos_coords[(b * II + idx) * 3 + 0];
                s_nc[1] = pos_coords[(b * II + idx) * 3 + 1];
                s_nc[2] = pos_coords[(b * II + idx) * 3 + 2];
            } else {
                s_nc[0] = 0.f; s_nc[1] = 0.f; s_nc[2] = 0.f;
            }
        }
    }
    __syncthreads();
    if (t < EE) {
        float ne = fmaf(s_nc[2], Wp[t * 3 + 2],
                   fmaf(s_nc[1], Wp[t * 3 + 1],
                   fmaf(s_nc[0], Wp[t * 3 + 0], bp[t])));
        s_diff[t] = g_pe[bi * EE + t] - ne;
    }
    __syncthreads();
    if (t < HH) {
        float a0 = 0.f, a1 = 0.f, a2 = 0.f, a3 = 0.f;
        const float* w = Wd1 + t * EE;
        for (int e = 0; e < EE; e += 4) {
            a0 = fmaf(s_diff[e],     w[e],     a0);
            a1 = fmaf(s_diff[e + 1], w[e + 1], a1);
            a2 = fmaf(s_diff[e + 2], w[e + 2], a2);
            a3 = fmaf(s_diff[e + 3], w[e + 3], a3);
        }
        g_v2[bi * HH + t] = ((a0 + a1) + (a2 + a3)) + bd1[t];
    }
}

// ---------------------------------------------------------------------------
// K4: refined logits, k-split.  grid 512 x 128 (same layout as k_maskbits)
// ---------------------------------------------------------------------------
__global__ __launch_bounds__(128) void k_refine(const float* __restrict__ Wd2,
                                                const float* __restrict__ bd2,
                                                float* __restrict__ out) {
    __shared__ float s_v[16 * 66];
    __shared__ float sb;
    int t = threadIdx.x;
    int b = blockIdx.x >> 8;
    int ig = (blockIdx.x >> 7) & 1;
    int chunk = blockIdx.x & 127;

    for (int idx = t; idx < 16 * HH; idx += 128) {
        int ii = idx >> 6, k = idx & 63;
        s_v[ii * 66 + k + (k >> 5)] = g_v2[b * II * HH + (ig * 16 + ii) * HH + k];
    }
    if (t == 0) sb = bd2[0];
    __syncthreads();

    int w = t >> 5, lane = t & 31;
    int p = lane & 15, h = lane >> 4;
    int n = (chunk << 6) + (w << 4) + p;
    int koff = h << 5;

    const float* up = g_u + ((size_t)(b * NN + n)) * HH + koff;
    float uu[32], swr[32];
#pragma unroll
    for (int k = 0; k < 32; k += 4) {
        float4 v = *(const float4*)(up + k);
        uu[k] = v.x; uu[k + 1] = v.y; uu[k + 2] = v.z; uu[k + 3] = v.w;
        float4 wv = *(const float4*)(Wd2 + koff + k);
        swr[k] = wv.x; swr[k + 1] = wv.y; swr[k + 2] = wv.z; swr[k + 3] = wv.w;
    }

#pragma unroll 1
    for (int ii = 0; ii < 16; ii++) {
        const float* vv = s_v + ii * 66 + h * 33;
        float a0 = 0.f, a1 = 0.f, a2 = 0.f, a3 = 0.f;
#pragma unroll
        for (int k = 0; k < 32; k += 4) {
            a0 = fmaf(fmaxf(uu[k]     + vv[k],     0.f), swr[k],     a0);
            a1 = fmaf(fmaxf(uu[k + 1] + vv[k + 1], 0.f), swr[k + 1], a1);
            a2 = fmaf(fmaxf(uu[k + 2] + vv[k + 2], 0.f), swr[k + 2], a2);
            a3 = fmaf(fmaxf(uu[k + 3] + vv[k + 3], 0.f), swr[k + 3], a3);
        }
        float tot = (a0 + a1) + (a2 + a3);
        tot += __shfl_xor_sync(0xffffffffu, tot, 16);
        if (h == 0)
            out[((size_t)(b * II + ig * 16 + ii) << 13) + n] = tot + sb;
    }
}

// ---------------------------------------------------------------------------
extern "C" void kernel_launch(void* const* d_in, const int* in_sizes, int n_in,
                              void* d_out, int out_size) {
    const float* points     = (const float*)d_in[0];
    const float* pos_coords = (const float*)d_in[1];
    const float* W1  = (const float*)d_in[2];
    const float* A1  = (const float*)d_in[3];
    const float* B1  = (const float*)d_in[4];
    const float* W2  = (const float*)d_in[5];
    const float* A2  = (const float*)d_in[6];
    const float* B2  = (const float*)d_in[7];
    const float* Wp  = (const float*)d_in[8];
    const float* bp  = (const float*)d_in[9];
    const float* Wd1 = (const float*)d_in[10];
    const float* bd1 = (const float*)d_in[11];
    const float* Wd2 = (const float*)d_in[12];
    const float* bd2 = (const float*)d_in[13];

    float* out_refined = (float*)d_out;                         // [2,32,8192]
    float* out_pf;                                              // [2,8192,128]
    const int need = BB * II * NN + BB * NN * EE;
    if (out_size >= need) {
        out_pf = (float*)d_out + (size_t)BB * II * NN;
    } else {
        cudaGetSymbolAddress((void**)&out_pf, g_pf_fallback);
    }

    (void)in_sizes; (void)n_in;

    k_prep<<<67, 256>>>(Wd1, W2, B2, pos_coords, Wp, bp, bd1);
    k_encoder<<<512, 128>>>(points, W1, A1, B1, W2, A2, B2, out_pf);
    k_maskbits<<<512, 128>>>(Wd2, bd2);
    k_inter<<<16, 1024>>>();
    k_select<<<64, 128>>>(pos_coords, Wp, bp, Wd1, bd1);
    k_refine<<<512, 128>>>(Wd2, bd2, out_refined);
}